// round 14
// baseline (speedup 1.0000x reference)
#include <cuda_runtime.h>
#include <cuda_fp16.h>
#include <cstdint>

#define B_ROWS 8192
#define P_DIM 512
#define C_CLASSES 1000
#define C_PAD 1024

#define BM 128
#define BN 128
#define BK 32
#define NCHUNK (P_DIM / BK)   // 16
#define NSTAGE 3
#define LDA 40                 // elements; 80B row stride, conflict-free LDSM
#define LDB 40

#define A_STAGE_BYTES (BM * LDA * 2)   // 10240
#define B_STAGE_BYTES (BN * LDB * 2)   // 10240
#define STAGE_BYTES (A_STAGE_BYTES + B_STAGE_BYTES)   // 20480
#define SMEM_TOTAL (NSTAGE * STAGE_BYTES + 16)        // 61456 -> 3 CTAs/SM

#define N_TILES 512
#define GRID_CTAS 444          // 148 SMs * 3 CTAs

// ---- scratch ----
__device__ __half g_xh[B_ROWS * P_DIM];
__device__ __half g_mh[C_PAD * P_DIM];
__device__ float g_fx[B_ROWS];     // 2 * r_b
__device__ float g_xsq[B_ROWS];
__device__ float g_msq[C_PAD];
__device__ unsigned g_tile_ctr;

// ======================= PTX helpers =======================
__device__ __forceinline__ uint32_t smem_u32(const void* p) {
    uint32_t a;
    asm("{ .reg .u64 t; cvta.to.shared.u64 t, %1; cvt.u32.u64 %0, t; }" : "=r"(a) : "l"(p));
    return a;
}
__device__ __forceinline__ void cp_async16(uint32_t dst, const void* src) {
    asm volatile("cp.async.cg.shared.global [%0], [%1], 16;" :: "r"(dst), "l"(src) : "memory");
}
__device__ __forceinline__ void cp_commit() {
    asm volatile("cp.async.commit_group;" ::: "memory");
}
__device__ __forceinline__ void cp_wait1() {
    asm volatile("cp.async.wait_group 1;" ::: "memory");
}
__device__ __forceinline__ void cp_wait0() {
    asm volatile("cp.async.wait_group 0;" ::: "memory");
}
__device__ __forceinline__ void ldsm_x4(uint32_t& r0, uint32_t& r1, uint32_t& r2, uint32_t& r3,
                                        uint32_t addr) {
    asm volatile("ldmatrix.sync.aligned.m8n8.x4.shared.b16 {%0,%1,%2,%3}, [%4];"
                 : "=r"(r0), "=r"(r1), "=r"(r2), "=r"(r3) : "r"(addr));
}
// fp16 x fp16 -> fp16 accum
__device__ __forceinline__ void mma16816h(uint32_t c[2], const uint32_t a[4], const uint32_t b[2]) {
    asm volatile(
        "mma.sync.aligned.m16n8k16.row.col.f16.f16.f16.f16 "
        "{%0,%1}, {%2,%3,%4,%5}, {%6,%7}, {%0,%1};\n"
        : "+r"(c[0]), "+r"(c[1])
        : "r"(a[0]), "r"(a[1]), "r"(a[2]), "r"(a[3]), "r"(b[0]), "r"(b[1]));
}

// ======================= fused prep kernel =======================
// blocks [0,128): class rows (8/block). blocks [128,1152): x rows (8/block).
__global__ void prep_all(const float* __restrict__ x, const float* __restrict__ means) {
    const int wid = threadIdx.x >> 5, lane = threadIdx.x & 31;
    if (blockIdx.x == 0 && threadIdx.x == 0) g_tile_ctr = 0;   // reset stealer

    if (blockIdx.x < 128) {
        const int c = blockIdx.x * 8 + wid;
        float4 v[4];
        float ss = 0.0f;
        if (c < C_CLASSES) {
            const float4* src = (const float4*)(means + (size_t)c * P_DIM);
            #pragma unroll
            for (int i = 0; i < 4; i++) {
                v[i] = src[lane + i * 32];
                ss += v[i].x * v[i].x + v[i].y * v[i].y + v[i].z * v[i].z + v[i].w * v[i].w;
            }
        } else {
            #pragma unroll
            for (int i = 0; i < 4; i++) v[i] = make_float4(0.f, 0.f, 0.f, 0.f);
        }
        #pragma unroll
        for (int o = 16; o > 0; o >>= 1) ss += __shfl_xor_sync(0xffffffffu, ss, o);

        uint2* dst = (uint2*)(g_mh + (size_t)c * P_DIM);
        #pragma unroll
        for (int i = 0; i < 4; i++) {
            __half2 lo = __floats2half2_rn(v[i].x, v[i].y);
            __half2 hi = __floats2half2_rn(v[i].z, v[i].w);
            uint2 p; p.x = *(uint32_t*)&lo; p.y = *(uint32_t*)&hi;
            dst[lane + i * 32] = p;
        }
        if (lane == 0) g_msq[c] = ss;
    } else {
        const int b = (blockIdx.x - 128) * 8 + wid;
        float sc = 0.0f;
        {
            const float4* m0 = (const float4*)means;
            #pragma unroll
            for (int i = 0; i < 4; i++) {
                float4 m = m0[lane + i * 32];
                sc += m.x * m.x + m.y * m.y + m.z * m.z + m.w * m.w;
            }
            #pragma unroll
            for (int o = 16; o > 0; o >>= 1) sc += __shfl_xor_sync(0xffffffffu, sc, o);
            sc = sqrtf(sc);
        }

        const float4* src = (const float4*)(x + (size_t)b * P_DIM);
        float4 v[4];
        float ss = 0.0f;
        #pragma unroll
        for (int i = 0; i < 4; i++) {
            v[i] = src[lane + i * 32];
            ss += v[i].x * v[i].x + v[i].y * v[i].y + v[i].z * v[i].z + v[i].w * v[i].w;
        }
        #pragma unroll
        for (int o = 16; o > 0; o >>= 1) ss += __shfl_xor_sync(0xffffffffu, ss, o);

        uint2* dst = (uint2*)(g_xh + (size_t)b * P_DIM);
        #pragma unroll
        for (int i = 0; i < 4; i++) {
            __half2 lo = __floats2half2_rn(v[i].x, v[i].y);
            __half2 hi = __floats2half2_rn(v[i].z, v[i].w);
            uint2 p; p.x = *(uint32_t*)&lo; p.y = *(uint32_t*)&hi;
            dst[lane + i * 32] = p;
        }
        if (lane == 0) {
            float norm = sqrtf(ss);
            float r = sc / (norm + 1e-10f);
            g_fx[b] = 2.0f * r;
            float tn = norm * r;
            g_xsq[b] = tn * tn;
        }
    }
}

// ======================= persistent fp16 HMMA GEMM, 3 CTAs/SM, depth-2 prefetch =====
// 444 persistent CTAs steal 512 tiles. 256 threads = 8 warps, 4(m) x 2(n), warptile 32x64.
// BK=32, 3 stages, wait_group 1 -> loads run 2 chunks ahead of compute.
__global__ __launch_bounds__(256, 3) void gemm_logits(float* __restrict__ out) {
    extern __shared__ __align__(16) char smem_raw[];
    const uint32_t sbase = smem_u32(smem_raw);
    unsigned* tile_bcast = (unsigned*)(smem_raw + NSTAGE * STAGE_BYTES);

    const int t = threadIdx.x;
    const int warp = t >> 5, lane = t & 31;
    const int wm = warp & 3;    // m-warp 0..3
    const int wn = warp >> 2;   // n-warp 0..1
    const int grp = lane >> 2, tid4 = lane & 3;

    // tile-invariant cp.async mapping: A = 512 16B-chunks, B = 512; 4 per thread.
    uint32_t src_inv[4];
    uint32_t dsts[4];
    #pragma unroll
    for (int i = 0; i < 4; i++) {
        int v = t + i * 256;
        int v2 = v & 511;
        int r = v2 >> 2, cc = (v2 & 3) * 8;
        src_inv[i] = (uint32_t)(r * P_DIM + cc);
        dsts[i] = (uint32_t)(r * (i < 2 ? LDA : LDB) + cc) * 2 + (i < 2 ? 0u : (uint32_t)A_STAGE_BYTES);
    }

    // LDSM lane addressing
    const int lq = lane >> 3, lr = lane & 7;
    const uint32_t a_lane_off =
        (uint32_t)((wm * 32 + (lq & 1) * 8 + lr) * LDA + (lq >> 1) * 8) * 2;
    const uint32_t b_lane_off =
        A_STAGE_BYTES + (uint32_t)((wn * 64 + (lq >> 1) * 8 + lr) * LDB + (lq & 1) * 8) * 2;

    for (;;) {
        if (t == 0) *tile_bcast = atomicAdd(&g_tile_ctr, 1u);
        __syncthreads();     // broadcast + guards buffer reuse across tiles
        const unsigned tile = *tile_bcast;
        if (tile >= N_TILES) break;

        const int bm = (int)(tile >> 3) * BM;
        const int bn = (int)(tile & 7) * BN;
        const __half* abase = g_xh + (size_t)bm * P_DIM;
        const __half* bbase = g_mh + (size_t)bn * P_DIM;

        uint32_t acc[2][8][2];
        #pragma unroll
        for (int mi = 0; mi < 2; mi++)
            #pragma unroll
            for (int ni = 0; ni < 8; ni++) {
                acc[mi][ni][0] = 0u;
                acc[mi][ni][1] = 0u;
            }

        auto issue_stage = [&](int c) {
            const uint32_t st = sbase + (c % NSTAGE) * STAGE_BYTES;
            const int koff = c * BK;
            #pragma unroll
            for (int i = 0; i < 4; i++)
                cp_async16(st + dsts[i], (i < 2 ? abase : bbase) + src_inv[i] + koff);
        };

        issue_stage(0); cp_commit();
        issue_stage(1); cp_commit();

        #pragma unroll 1
        for (int c = 0; c < NCHUNK; c++) {
            if (c == NCHUNK - 1) cp_wait0(); else cp_wait1();   // stage c landed; c+1 may fly
            __syncthreads();     // all warps past chunk c-1 reads -> buffer (c+2)%3 free

            if (c + 2 < NCHUNK) { issue_stage(c + 2); cp_commit(); }

            const uint32_t st = sbase + (c % NSTAGE) * STAGE_BYTES;
            const uint32_t ast = st + a_lane_off;
            const uint32_t bst = st + b_lane_off;

            #pragma unroll
            for (int kk = 0; kk < BK; kk += 16) {
                uint32_t a[2][4];
                #pragma unroll
                for (int mi = 0; mi < 2; mi++)
                    ldsm_x4(a[mi][0], a[mi][1], a[mi][2], a[mi][3],
                            ast + (uint32_t)(mi * 16 * LDA + kk) * 2);
                uint32_t b[8][2];
                #pragma unroll
                for (int ng = 0; ng < 4; ng++)
                    ldsm_x4(b[ng * 2][0], b[ng * 2][1], b[ng * 2 + 1][0], b[ng * 2 + 1][1],
                            bst + (uint32_t)(ng * 16 * LDB + kk) * 2);
                #pragma unroll
                for (int mi = 0; mi < 2; mi++)
                    #pragma unroll
                    for (int ni = 0; ni < 8; ni++)
                        mma16816h(acc[mi][ni], a[mi], b[ni]);
            }
        }

        // ---- fused epilogue: out = fx_b * cross - xsq_b - msq_c ----
        #pragma unroll
        for (int mi = 0; mi < 2; mi++) {
            int row0 = bm + wm * 32 + mi * 16 + grp;
            float f0 = g_fx[row0], xs0 = g_xsq[row0];
            float f1 = g_fx[row0 + 8], xs1 = g_xsq[row0 + 8];
            #pragma unroll
            for (int ni = 0; ni < 8; ni++) {
                int col = bn + wn * 64 + ni * 8 + tid4 * 2;
                __half2 h0 = *(__half2*)&acc[mi][ni][0];
                __half2 h1 = *(__half2*)&acc[mi][ni][1];
                float2 c0 = __half22float2(h0);
                float2 c1 = __half22float2(h1);
                if (col < C_CLASSES) {
                    float ms = g_msq[col];
                    out[(size_t)row0 * C_CLASSES + col]       = f0 * c0.x - xs0 - ms;
                    out[(size_t)(row0 + 8) * C_CLASSES + col] = f1 * c1.x - xs1 - ms;
                }
                if (col + 1 < C_CLASSES) {
                    float ms = g_msq[col + 1];
                    out[(size_t)row0 * C_CLASSES + col + 1]       = f0 * c0.y - xs0 - ms;
                    out[(size_t)(row0 + 8) * C_CLASSES + col + 1] = f1 * c1.y - xs1 - ms;
                }
            }
        }
    }
}

extern "C" void kernel_launch(void* const* d_in, const int* in_sizes, int n_in,
                              void* d_out, int out_size) {
    const float* x = (const float*)d_in[0];      // (8192, 512)
    const float* means = (const float*)d_in[1];  // (1000, 512)
    float* out = (float*)d_out;                  // (8192, 1000)
    (void)in_sizes; (void)n_in; (void)out_size;

    static int smem_set = 0;
    if (!smem_set) {
        cudaFuncSetAttribute(gemm_logits, cudaFuncAttributeMaxDynamicSharedMemorySize, SMEM_TOTAL);
        smem_set = 1;
    }

    prep_all<<<128 + B_ROWS / 8, 256>>>(x, means);
    gemm_logits<<<GRID_CTAS, 256, SMEM_TOTAL>>>(out);
}

// round 15
// speedup vs baseline: 1.0639x; 1.0639x over previous
#include <cuda_runtime.h>
#include <cuda_fp16.h>
#include <cstdint>

#define B_ROWS 8192
#define P_DIM 512
#define C_CLASSES 1000
#define C_PAD 1024

#define BM 128
#define BN 64
#define BK 64
#define NCHUNK (P_DIM / BK)   // 8
#define NSTAGE 2
#define LDA 72                 // elements; 144B row stride, conflict-free LDSM
#define LDB 72

#define A_STAGE_BYTES (BM * LDA * 2)   // 18432
#define B_STAGE_BYTES (BN * LDB * 2)   // 9216
#define STAGE_BYTES (A_STAGE_BYTES + B_STAGE_BYTES)   // 27648
#define SMEM_TOTAL (NSTAGE * STAGE_BYTES + 16)        // 55312 -> 4 CTAs/SM

#define N_TILES 1024           // (8192/128) * (1024/64) = 64 * 16
#define GRID_CTAS 592          // 148 SMs * 4 CTAs

// ---- scratch ----
__device__ __half g_xh[B_ROWS * P_DIM];
__device__ __half g_mh[C_PAD * P_DIM];
__device__ float g_fx[B_ROWS];     // 2 * r_b
__device__ float g_xsq[B_ROWS];
__device__ float g_msq[C_PAD];
__device__ unsigned g_tile_ctr;

// ======================= PTX helpers =======================
__device__ __forceinline__ uint32_t smem_u32(const void* p) {
    uint32_t a;
    asm("{ .reg .u64 t; cvta.to.shared.u64 t, %1; cvt.u32.u64 %0, t; }" : "=r"(a) : "l"(p));
    return a;
}
__device__ __forceinline__ void cp_async16(uint32_t dst, const void* src) {
    asm volatile("cp.async.cg.shared.global [%0], [%1], 16;" :: "r"(dst), "l"(src) : "memory");
}
__device__ __forceinline__ void cp_commit() {
    asm volatile("cp.async.commit_group;" ::: "memory");
}
__device__ __forceinline__ void cp_wait0() {
    asm volatile("cp.async.wait_group 0;" ::: "memory");
}
__device__ __forceinline__ void ldsm_x4(uint32_t& r0, uint32_t& r1, uint32_t& r2, uint32_t& r3,
                                        uint32_t addr) {
    asm volatile("ldmatrix.sync.aligned.m8n8.x4.shared.b16 {%0,%1,%2,%3}, [%4];"
                 : "=r"(r0), "=r"(r1), "=r"(r2), "=r"(r3) : "r"(addr));
}
// fp16 x fp16 -> fp16 accum
__device__ __forceinline__ void mma16816h(uint32_t c[2], const uint32_t a[4], const uint32_t b[2]) {
    asm volatile(
        "mma.sync.aligned.m16n8k16.row.col.f16.f16.f16.f16 "
        "{%0,%1}, {%2,%3,%4,%5}, {%6,%7}, {%0,%1};\n"
        : "+r"(c[0]), "+r"(c[1])
        : "r"(a[0]), "r"(a[1]), "r"(a[2]), "r"(a[3]), "r"(b[0]), "r"(b[1]));
}

// ======================= fused prep kernel =======================
// blocks [0,128): class rows (8/block). blocks [128,1152): x rows (8/block).
__global__ void prep_all(const float* __restrict__ x, const float* __restrict__ means) {
    const int wid = threadIdx.x >> 5, lane = threadIdx.x & 31;
    if (blockIdx.x == 0 && threadIdx.x == 0) g_tile_ctr = 0;   // reset stealer

    if (blockIdx.x < 128) {
        const int c = blockIdx.x * 8 + wid;
        float4 v[4];
        float ss = 0.0f;
        if (c < C_CLASSES) {
            const float4* src = (const float4*)(means + (size_t)c * P_DIM);
            #pragma unroll
            for (int i = 0; i < 4; i++) {
                v[i] = src[lane + i * 32];
                ss += v[i].x * v[i].x + v[i].y * v[i].y + v[i].z * v[i].z + v[i].w * v[i].w;
            }
        } else {
            #pragma unroll
            for (int i = 0; i < 4; i++) v[i] = make_float4(0.f, 0.f, 0.f, 0.f);
        }
        #pragma unroll
        for (int o = 16; o > 0; o >>= 1) ss += __shfl_xor_sync(0xffffffffu, ss, o);

        uint2* dst = (uint2*)(g_mh + (size_t)c * P_DIM);
        #pragma unroll
        for (int i = 0; i < 4; i++) {
            __half2 lo = __floats2half2_rn(v[i].x, v[i].y);
            __half2 hi = __floats2half2_rn(v[i].z, v[i].w);
            uint2 p; p.x = *(uint32_t*)&lo; p.y = *(uint32_t*)&hi;
            dst[lane + i * 32] = p;
        }
        if (lane == 0) g_msq[c] = ss;
    } else {
        const int b = (blockIdx.x - 128) * 8 + wid;
        float sc = 0.0f;
        {
            const float4* m0 = (const float4*)means;
            #pragma unroll
            for (int i = 0; i < 4; i++) {
                float4 m = m0[lane + i * 32];
                sc += m.x * m.x + m.y * m.y + m.z * m.z + m.w * m.w;
            }
            #pragma unroll
            for (int o = 16; o > 0; o >>= 1) sc += __shfl_xor_sync(0xffffffffu, sc, o);
            sc = sqrtf(sc);
        }

        const float4* src = (const float4*)(x + (size_t)b * P_DIM);
        float4 v[4];
        float ss = 0.0f;
        #pragma unroll
        for (int i = 0; i < 4; i++) {
            v[i] = src[lane + i * 32];
            ss += v[i].x * v[i].x + v[i].y * v[i].y + v[i].z * v[i].z + v[i].w * v[i].w;
        }
        #pragma unroll
        for (int o = 16; o > 0; o >>= 1) ss += __shfl_xor_sync(0xffffffffu, ss, o);

        uint2* dst = (uint2*)(g_xh + (size_t)b * P_DIM);
        #pragma unroll
        for (int i = 0; i < 4; i++) {
            __half2 lo = __floats2half2_rn(v[i].x, v[i].y);
            __half2 hi = __floats2half2_rn(v[i].z, v[i].w);
            uint2 p; p.x = *(uint32_t*)&lo; p.y = *(uint32_t*)&hi;
            dst[lane + i * 32] = p;
        }
        if (lane == 0) {
            float norm = sqrtf(ss);
            float r = sc / (norm + 1e-10f);
            g_fx[b] = 2.0f * r;
            float tn = norm * r;
            g_xsq[b] = tn * tn;
        }
    }
}

// ======================= persistent fp16 HMMA GEMM, 4 CTAs/SM, 128x64 tiles ========
// 592 persistent CTAs steal 1024 tiles -> makespan ~2 small tiles, ~86% packing.
// 256 threads = 8 warps, 4(m) x 2(n), warptile 32x32.
__global__ __launch_bounds__(256, 4) void gemm_logits(float* __restrict__ out) {
    extern __shared__ __align__(16) char smem_raw[];
    const uint32_t sbase = smem_u32(smem_raw);
    unsigned* tile_bcast = (unsigned*)(smem_raw + NSTAGE * STAGE_BYTES);

    const int t = threadIdx.x;
    const int warp = t >> 5, lane = t & 31;
    const int wm = warp & 3;    // m-warp 0..3
    const int wn = warp >> 2;   // n-warp 0..1
    const int grp = lane >> 2, tid4 = lane & 3;

    // cp.async mapping: A = 1024 16B-chunks, B = 512; 6 per thread (256 thr).
    uint32_t src_inv[6];
    uint32_t dsts[6];
    #pragma unroll
    for (int i = 0; i < 6; i++) {
        int v = t + i * 256;            // 0..1535
        if (v < 1024) {                 // A chunk
            int r = v >> 3, cc = (v & 7) * 8;
            src_inv[i] = (uint32_t)(r * P_DIM + cc);
            dsts[i] = (uint32_t)(r * LDA + cc) * 2;
        } else {                        // B chunk
            int v2 = v - 1024;          // 0..511
            int r = v2 >> 3, cc = (v2 & 7) * 8;
            src_inv[i] = (uint32_t)(r * P_DIM + cc);
            dsts[i] = (uint32_t)A_STAGE_BYTES + (uint32_t)(r * LDB + cc) * 2;
        }
    }

    // LDSM lane addressing
    const int lq = lane >> 3, lr = lane & 7;
    const uint32_t a_lane_off =
        (uint32_t)((wm * 32 + (lq & 1) * 8 + lr) * LDA + (lq >> 1) * 8) * 2;
    const uint32_t b_lane_off =
        A_STAGE_BYTES + (uint32_t)((wn * 32 + (lq >> 1) * 8 + lr) * LDB + (lq & 1) * 8) * 2;

    for (;;) {
        if (t == 0) *tile_bcast = atomicAdd(&g_tile_ctr, 1u);
        __syncthreads();     // broadcast + guards buffer reuse across tiles
        const unsigned tile = *tile_bcast;
        if (tile >= N_TILES) break;

        const int bm = (int)(tile >> 4) * BM;        // 64 m-blocks
        const int bn = (int)(tile & 15) * BN;        // 16 n-blocks
        const __half* abase = g_xh + (size_t)bm * P_DIM;
        const __half* bbase = g_mh + (size_t)bn * P_DIM;

        uint32_t acc[2][4][2];   // packed f16x2 accumulators
        #pragma unroll
        for (int mi = 0; mi < 2; mi++)
            #pragma unroll
            for (int ni = 0; ni < 4; ni++) {
                acc[mi][ni][0] = 0u;
                acc[mi][ni][1] = 0u;
            }

        auto issue_stage = [&](int c) {
            const uint32_t st = sbase + (c & 1) * STAGE_BYTES;
            const int koff = c * BK;
            #pragma unroll
            for (int i = 0; i < 6; i++)
                cp_async16(st + dsts[i], (i < 4 ? abase : bbase) + src_inv[i] + koff);
        };

        issue_stage(0); cp_commit();

        #pragma unroll 1
        for (int c = 0; c < NCHUNK; c++) {
            cp_wait0();          // stage c landed
            __syncthreads();     // all warps past chunk c-1 reads -> other buffer free

            if (c + 1 < NCHUNK) { issue_stage(c + 1); cp_commit(); }

            const uint32_t st = sbase + (c & 1) * STAGE_BYTES;
            const uint32_t ast = st + a_lane_off;
            const uint32_t bst = st + b_lane_off;

            #pragma unroll
            for (int kk = 0; kk < BK; kk += 16) {
                uint32_t a[2][4];
                #pragma unroll
                for (int mi = 0; mi < 2; mi++)
                    ldsm_x4(a[mi][0], a[mi][1], a[mi][2], a[mi][3],
                            ast + (uint32_t)(mi * 16 * LDA + kk) * 2);
                uint32_t b[4][2];
                #pragma unroll
                for (int ng = 0; ng < 2; ng++)
                    ldsm_x4(b[ng * 2][0], b[ng * 2][1], b[ng * 2 + 1][0], b[ng * 2 + 1][1],
                            bst + (uint32_t)(ng * 16 * LDB + kk) * 2);
                #pragma unroll
                for (int mi = 0; mi < 2; mi++)
                    #pragma unroll
                    for (int ni = 0; ni < 4; ni++)
                        mma16816h(acc[mi][ni], a[mi], b[ni]);
            }
        }

        // ---- fused epilogue: out = fx_b * cross - xsq_b - msq_c ----
        #pragma unroll
        for (int mi = 0; mi < 2; mi++) {
            int row0 = bm + wm * 32 + mi * 16 + grp;
            float f0 = g_fx[row0], xs0 = g_xsq[row0];
            float f1 = g_fx[row0 + 8], xs1 = g_xsq[row0 + 8];
            #pragma unroll
            for (int ni = 0; ni < 4; ni++) {
                int col = bn + wn * 32 + ni * 8 + tid4 * 2;
                __half2 h0 = *(__half2*)&acc[mi][ni][0];
                __half2 h1 = *(__half2*)&acc[mi][ni][1];
                float2 c0 = __half22float2(h0);
                float2 c1 = __half22float2(h1);
                if (col < C_CLASSES) {
                    float ms = g_msq[col];
                    out[(size_t)row0 * C_CLASSES + col]       = f0 * c0.x - xs0 - ms;
                    out[(size_t)(row0 + 8) * C_CLASSES + col] = f1 * c1.x - xs1 - ms;
                }
                if (col + 1 < C_CLASSES) {
                    float ms = g_msq[col + 1];
                    out[(size_t)row0 * C_CLASSES + col + 1]       = f0 * c0.y - xs0 - ms;
                    out[(size_t)(row0 + 8) * C_CLASSES + col + 1] = f1 * c1.y - xs1 - ms;
                }
            }
        }
    }
}

extern "C" void kernel_launch(void* const* d_in, const int* in_sizes, int n_in,
                              void* d_out, int out_size) {
    const float* x = (const float*)d_in[0];      // (8192, 512)
    const float* means = (const float*)d_in[1];  // (1000, 512)
    float* out = (float*)d_out;                  // (8192, 1000)
    (void)in_sizes; (void)n_in; (void)out_size;

    static int smem_set = 0;
    if (!smem_set) {
        cudaFuncSetAttribute(gemm_logits, cudaFuncAttributeMaxDynamicSharedMemorySize, SMEM_TOTAL);
        smem_set = 1;
    }

    prep_all<<<128 + B_ROWS / 8, 256>>>(x, means);
    gemm_logits<<<GRID_CTAS, 256, SMEM_TOTAL>>>(out);
}

// round 16
// speedup vs baseline: 1.1042x; 1.0378x over previous
#include <cuda_runtime.h>
#include <cuda_fp16.h>
#include <cstdint>

#define B_ROWS 8192
#define P_DIM 512
#define C_CLASSES 1000
#define C_PAD 1024

#define BM 128
#define BN 128
#define BK 64
#define NCHUNK (P_DIM / BK)   // 8
#define NSTAGE 2
#define LDA 72                 // elements; 144B row stride, conflict-free LDSM
#define LDB 72

#define A_STAGE_BYTES (BM * LDA * 2)   // 18432
#define B_STAGE_BYTES (BN * LDB * 2)   // 18432
#define STAGE_BYTES (A_STAGE_BYTES + B_STAGE_BYTES)   // 36864
#define SMEM_TOTAL (NSTAGE * STAGE_BYTES + 16)        // 73744 -> 3 CTAs/SM

#define N_TILES 512
#define GRID_CTAS 444          // 148 SMs * 3 CTAs

// ---- scratch ----
__device__ __half g_xh[B_ROWS * P_DIM];
__device__ __half g_mh[C_PAD * P_DIM];
__device__ float g_fx[B_ROWS];     // 2 * r_b
__device__ float g_xsq[B_ROWS];
__device__ float g_msq[C_PAD];
__device__ unsigned g_tile_ctr;

// ======================= PTX helpers =======================
__device__ __forceinline__ uint32_t smem_u32(const void* p) {
    uint32_t a;
    asm("{ .reg .u64 t; cvta.to.shared.u64 t, %1; cvt.u32.u64 %0, t; }" : "=r"(a) : "l"(p));
    return a;
}
__device__ __forceinline__ void cp_async16(uint32_t dst, const void* src) {
    asm volatile("cp.async.cg.shared.global [%0], [%1], 16;" :: "r"(dst), "l"(src) : "memory");
}
__device__ __forceinline__ void cp_commit() {
    asm volatile("cp.async.commit_group;" ::: "memory");
}
__device__ __forceinline__ void cp_wait0() {
    asm volatile("cp.async.wait_group 0;" ::: "memory");
}
__device__ __forceinline__ void ldsm_x4(uint32_t& r0, uint32_t& r1, uint32_t& r2, uint32_t& r3,
                                        uint32_t addr) {
    asm volatile("ldmatrix.sync.aligned.m8n8.x4.shared.b16 {%0,%1,%2,%3}, [%4];"
                 : "=r"(r0), "=r"(r1), "=r"(r2), "=r"(r3) : "r"(addr));
}
// fp16 x fp16 -> fp16 accum
__device__ __forceinline__ void mma16816h(uint32_t c[2], const uint32_t a[4], const uint32_t b[2]) {
    asm volatile(
        "mma.sync.aligned.m16n8k16.row.col.f16.f16.f16.f16 "
        "{%0,%1}, {%2,%3,%4,%5}, {%6,%7}, {%0,%1};\n"
        : "+r"(c[0]), "+r"(c[1])
        : "r"(a[0]), "r"(a[1]), "r"(a[2]), "r"(a[3]), "r"(b[0]), "r"(b[1]));
}

// ======================= fused prep kernel (2 rows per warp) =======================
// blocks [0,64): class rows (16/block). blocks [64,576): x rows (16/block).
__global__ void prep_all(const float* __restrict__ x, const float* __restrict__ means) {
    const int wid = threadIdx.x >> 5, lane = threadIdx.x & 31;
    if (blockIdx.x == 0 && threadIdx.x == 0) g_tile_ctr = 0;   // reset stealer

    if (blockIdx.x < 64) {
        const int c0 = blockIdx.x * 16 + wid * 2;
        #pragma unroll
        for (int rr = 0; rr < 2; rr++) {
            const int c = c0 + rr;
            float4 v[4];
            float ss = 0.0f;
            if (c < C_CLASSES) {
                const float4* src = (const float4*)(means + (size_t)c * P_DIM);
                #pragma unroll
                for (int i = 0; i < 4; i++) {
                    v[i] = src[lane + i * 32];
                    ss += v[i].x * v[i].x + v[i].y * v[i].y + v[i].z * v[i].z + v[i].w * v[i].w;
                }
            } else {
                #pragma unroll
                for (int i = 0; i < 4; i++) v[i] = make_float4(0.f, 0.f, 0.f, 0.f);
            }
            #pragma unroll
            for (int o = 16; o > 0; o >>= 1) ss += __shfl_xor_sync(0xffffffffu, ss, o);

            uint2* dst = (uint2*)(g_mh + (size_t)c * P_DIM);
            #pragma unroll
            for (int i = 0; i < 4; i++) {
                __half2 lo = __floats2half2_rn(v[i].x, v[i].y);
                __half2 hi = __floats2half2_rn(v[i].z, v[i].w);
                uint2 p; p.x = *(uint32_t*)&lo; p.y = *(uint32_t*)&hi;
                dst[lane + i * 32] = p;
            }
            if (lane == 0) g_msq[c] = ss;
        }
    } else {
        const int b0 = (blockIdx.x - 64) * 16 + wid * 2;
        // scale = ||means[0]|| once per warp (row 0 is L2-hot)
        float sc = 0.0f;
        {
            const float4* m0 = (const float4*)means;
            #pragma unroll
            for (int i = 0; i < 4; i++) {
                float4 m = m0[lane + i * 32];
                sc += m.x * m.x + m.y * m.y + m.z * m.z + m.w * m.w;
            }
            #pragma unroll
            for (int o = 16; o > 0; o >>= 1) sc += __shfl_xor_sync(0xffffffffu, sc, o);
            sc = sqrtf(sc);
        }

        // both rows' loads issued together for MLP=8
        float4 v[2][4];
        #pragma unroll
        for (int rr = 0; rr < 2; rr++) {
            const float4* src = (const float4*)(x + (size_t)(b0 + rr) * P_DIM);
            #pragma unroll
            for (int i = 0; i < 4; i++) v[rr][i] = src[lane + i * 32];
        }
        #pragma unroll
        for (int rr = 0; rr < 2; rr++) {
            float ss = 0.0f;
            #pragma unroll
            for (int i = 0; i < 4; i++)
                ss += v[rr][i].x * v[rr][i].x + v[rr][i].y * v[rr][i].y +
                      v[rr][i].z * v[rr][i].z + v[rr][i].w * v[rr][i].w;
            #pragma unroll
            for (int o = 16; o > 0; o >>= 1) ss += __shfl_xor_sync(0xffffffffu, ss, o);

            uint2* dst = (uint2*)(g_xh + (size_t)(b0 + rr) * P_DIM);
            #pragma unroll
            for (int i = 0; i < 4; i++) {
                __half2 lo = __floats2half2_rn(v[rr][i].x, v[rr][i].y);
                __half2 hi = __floats2half2_rn(v[rr][i].z, v[rr][i].w);
                uint2 p; p.x = *(uint32_t*)&lo; p.y = *(uint32_t*)&hi;
                dst[lane + i * 32] = p;
            }
            if (lane == 0) {
                float norm = sqrtf(ss);
                float r = sc / (norm + 1e-10f);
                g_fx[b0 + rr] = 2.0f * r;
                float tn = norm * r;
                g_xsq[b0 + rr] = tn * tn;
            }
        }
    }
}

// ======================= persistent fp16 HMMA GEMM, 3 CTAs/SM (R13 core) ===========
// 444 persistent CTAs steal 512 tiles. 256 threads = 8 warps, 4(m) x 2(n), warptile 32x64.
// BK=64, 2 stages, ONE sync per chunk.
__global__ __launch_bounds__(256, 3) void gemm_logits(float* __restrict__ out) {
    extern __shared__ __align__(16) char smem_raw[];
    const uint32_t sbase = smem_u32(smem_raw);
    unsigned* tile_bcast = (unsigned*)(smem_raw + NSTAGE * STAGE_BYTES);

    const int t = threadIdx.x;
    const int warp = t >> 5, lane = t & 31;
    const int wm = warp & 3;    // m-warp 0..3
    const int wn = warp >> 2;   // n-warp 0..1
    const int grp = lane >> 2, tid4 = lane & 3;

    // tile-invariant cp.async mapping: A = 1024 16B-chunks, B = 1024; 8 per thread.
    uint32_t src_inv[8];
    uint32_t dsts[8];
    #pragma unroll
    for (int i = 0; i < 8; i++) {
        int v = t + i * 256;
        int v2 = v & 1023;
        int r = v2 >> 3, cc = (v2 & 7) * 8;
        src_inv[i] = (uint32_t)(r * P_DIM + cc);
        dsts[i] = (uint32_t)(r * (i < 4 ? LDA : LDB) + cc) * 2 + (i < 4 ? 0u : (uint32_t)A_STAGE_BYTES);
    }

    // LDSM lane addressing
    const int lq = lane >> 3, lr = lane & 7;
    const uint32_t a_lane_off =
        (uint32_t)((wm * 32 + (lq & 1) * 8 + lr) * LDA + (lq >> 1) * 8) * 2;
    const uint32_t b_lane_off =
        A_STAGE_BYTES + (uint32_t)((wn * 64 + (lq >> 1) * 8 + lr) * LDB + (lq & 1) * 8) * 2;

    for (;;) {
        if (t == 0) *tile_bcast = atomicAdd(&g_tile_ctr, 1u);
        __syncthreads();     // broadcast + guards buffer reuse across tiles
        const unsigned tile = *tile_bcast;
        if (tile >= N_TILES) break;

        const int bm = (int)(tile >> 3) * BM;
        const int bn = (int)(tile & 7) * BN;
        const __half* abase = g_xh + (size_t)bm * P_DIM;
        const __half* bbase = g_mh + (size_t)bn * P_DIM;

        uint32_t acc[2][8][2];
        #pragma unroll
        for (int mi = 0; mi < 2; mi++)
            #pragma unroll
            for (int ni = 0; ni < 8; ni++) {
                acc[mi][ni][0] = 0u;
                acc[mi][ni][1] = 0u;
            }

        auto issue_stage = [&](int c) {
            const uint32_t st = sbase + (c & 1) * STAGE_BYTES;
            const int koff = c * BK;
            #pragma unroll
            for (int i = 0; i < 8; i++)
                cp_async16(st + dsts[i], (i < 4 ? abase : bbase) + src_inv[i] + koff);
        };

        issue_stage(0); cp_commit();

        #pragma unroll 1
        for (int c = 0; c < NCHUNK; c++) {
            cp_wait0();          // own stage-c copies landed
            __syncthreads();     // everyone's copies landed; chunk c-1 reads done

            if (c + 1 < NCHUNK) { issue_stage(c + 1); cp_commit(); }

            const uint32_t st = sbase + (c & 1) * STAGE_BYTES;
            const uint32_t ast = st + a_lane_off;
            const uint32_t bst = st + b_lane_off;

            #pragma unroll
            for (int kk = 0; kk < BK; kk += 16) {
                uint32_t a[2][4];
                #pragma unroll
                for (int mi = 0; mi < 2; mi++)
                    ldsm_x4(a[mi][0], a[mi][1], a[mi][2], a[mi][3],
                            ast + (uint32_t)(mi * 16 * LDA + kk) * 2);
                uint32_t b[8][2];
                #pragma unroll
                for (int ng = 0; ng < 4; ng++)
                    ldsm_x4(b[ng * 2][0], b[ng * 2][1], b[ng * 2 + 1][0], b[ng * 2 + 1][1],
                            bst + (uint32_t)(ng * 16 * LDB + kk) * 2);
                #pragma unroll
                for (int mi = 0; mi < 2; mi++)
                    #pragma unroll
                    for (int ni = 0; ni < 8; ni++)
                        mma16816h(acc[mi][ni], a[mi], b[ni]);
            }
        }

        // ---- fused epilogue: out = fx_b * cross - xsq_b - msq_c ----
        #pragma unroll
        for (int mi = 0; mi < 2; mi++) {
            int row0 = bm + wm * 32 + mi * 16 + grp;
            float f0 = g_fx[row0], xs0 = g_xsq[row0];
            float f1 = g_fx[row0 + 8], xs1 = g_xsq[row0 + 8];
            #pragma unroll
            for (int ni = 0; ni < 8; ni++) {
                int col = bn + wn * 64 + ni * 8 + tid4 * 2;
                __half2 h0 = *(__half2*)&acc[mi][ni][0];
                __half2 h1 = *(__half2*)&acc[mi][ni][1];
                float2 c0 = __half22float2(h0);
                float2 c1 = __half22float2(h1);
                if (col < C_CLASSES) {
                    float ms = g_msq[col];
                    out[(size_t)row0 * C_CLASSES + col]       = f0 * c0.x - xs0 - ms;
                    out[(size_t)(row0 + 8) * C_CLASSES + col] = f1 * c1.x - xs1 - ms;
                }
                if (col + 1 < C_CLASSES) {
                    float ms = g_msq[col + 1];
                    out[(size_t)row0 * C_CLASSES + col + 1]       = f0 * c0.y - xs0 - ms;
                    out[(size_t)(row0 + 8) * C_CLASSES + col + 1] = f1 * c1.y - xs1 - ms;
                }
            }
        }
    }
}

extern "C" void kernel_launch(void* const* d_in, const int* in_sizes, int n_in,
                              void* d_out, int out_size) {
    const float* x = (const float*)d_in[0];      // (8192, 512)
    const float* means = (const float*)d_in[1];  // (1000, 512)
    float* out = (float*)d_out;                  // (8192, 1000)
    (void)in_sizes; (void)n_in; (void)out_size;

    static int smem_set = 0;
    if (!smem_set) {
        cudaFuncSetAttribute(gemm_logits, cudaFuncAttributeMaxDynamicSharedMemorySize, SMEM_TOTAL);
        smem_set = 1;
    }

    prep_all<<<576, 256>>>(x, means);
    gemm_logits<<<GRID_CTAS, 256, SMEM_TOTAL>>>(out);
}